// round 2
// baseline (speedup 1.0000x reference)
#include <cuda_runtime.h>
#include <math.h>

#define D 128
#define GMAX 512
#define NMAX 50176   // 784 * 64, covers N=50000 rounded to BM multiple

// ---------------- scratch (static device allocations; no cudaMalloc) --------
__device__ float g_agg[NMAX * D];
__device__ float g_h[NMAX * D];
__device__ float g_h1[NMAX * D];
__device__ float g_h2[NMAX * D];
__device__ float g_sum[D];
__device__ float g_sq[D];
__device__ float g_scale[D];
__device__ float g_shift[D];
__device__ float g_pa1[GMAX * D];
__device__ float g_pa2[GMAX * D];
__device__ unsigned int g_pm1[GMAX * D];
__device__ unsigned int g_pm2[GMAX * D];

// ---------------- utility kernels ----------------
__global__ void zero_f(float* p, int n) {
    int i = blockIdx.x * blockDim.x + threadIdx.x;
    int stride = gridDim.x * blockDim.x;
    for (; i < n; i += stride) p[i] = 0.0f;
}

__global__ void zero_stats() {
    int f = threadIdx.x;
    if (f < D) { g_sum[f] = 0.0f; g_sq[f] = 0.0f; }
}

// ---------------- edge scatter: agg[dst] += x[src] ----------------
// one warp per edge: lane c handles features [4c, 4c+4)
__global__ void scatter_kernel(const float* __restrict__ x,
                               const int* __restrict__ ei,
                               float* __restrict__ agg, int n_edges, int n) {
    int t = blockIdx.x * blockDim.x + threadIdx.x;
    int e = t >> 5;
    if (e >= n_edges) return;
    int c = t & 31;
    int src = ei[e];
    int dst = ei[n_edges + e];
    if ((unsigned)src >= (unsigned)n || (unsigned)dst >= (unsigned)n) return;
    float4 v = ((const float4*)x)[(size_t)src * 32 + c];
    float* a = agg + (size_t)dst * D + c * 4;
    atomicAdd(a + 0, v.x);
    atomicAdd(a + 1, v.y);
    atomicAdd(a + 2, v.z);
    atomicAdd(a + 3, v.w);
}

// ---------------- GEMM 1: out = (agg + x) @ W + b ----------------
// BM=64 rows per block, 256 threads, K chunked by 32.
__global__ __launch_bounds__(256) void gemm_conv1(
    const float* __restrict__ agg, const float* __restrict__ x,
    const float* __restrict__ W, const float* __restrict__ b,
    float* __restrict__ out, int n) {
    __shared__ float Ws[32 * 128];
    __shared__ float As[32 * 65];
    int t = threadIdx.x;
    int warp = t >> 5, lane = t & 31;
    int row0 = blockIdx.x * 64;

    float acc[8][4];
#pragma unroll
    for (int i = 0; i < 8; i++)
#pragma unroll
        for (int j = 0; j < 4; j++) acc[i][j] = 0.0f;

    for (int kc = 0; kc < 4; kc++) {
#pragma unroll
        for (int i = 0; i < 16; i++) {
            int idx = t + i * 256;           // idx = kk*128 + col
            Ws[idx] = W[kc * 4096 + idx];
        }
#pragma unroll
        for (int i = 0; i < 8; i++) {
            int idx = t + i * 256;
            int row = idx >> 5;
            int kk = idx & 31;
            int r = row0 + row;
            float v = 0.0f;
            if (r < n) {
                size_t off = (size_t)r * 128 + kc * 32 + kk;
                v = agg[off] + x[off];
            }
            As[kk * 65 + row] = v;
        }
        __syncthreads();
#pragma unroll
        for (int kk = 0; kk < 32; kk++) {
            float4 w = *(const float4*)&Ws[kk * 128 + lane * 4];
#pragma unroll
            for (int i = 0; i < 8; i++) {
                float a = As[kk * 65 + warp * 8 + i];
                acc[i][0] += a * w.x;
                acc[i][1] += a * w.y;
                acc[i][2] += a * w.z;
                acc[i][3] += a * w.w;
            }
        }
        __syncthreads();
    }

    float4 bb = *(const float4*)&b[lane * 4];
#pragma unroll
    for (int i = 0; i < 8; i++) {
        int r = row0 + warp * 8 + i;
        if (r < n) {
            float4 o;
            o.x = acc[i][0] + bb.x;
            o.y = acc[i][1] + bb.y;
            o.z = acc[i][2] + bb.z;
            o.w = acc[i][3] + bb.w;
            *(float4*)&out[(size_t)r * 128 + lane * 4] = o;
        }
    }
}

// ---------------- BN stats: per-feature sum / sumsq ----------------
__global__ void bn_stats(const float* __restrict__ h, int n) {
    int f = threadIdx.x;   // 128 threads
    float s = 0.0f, q = 0.0f;
    for (int r = blockIdx.x; r < n; r += gridDim.x) {
        float v = h[(size_t)r * 128 + f];
        s += v;
        q += v * v;
    }
    atomicAdd(&g_sum[f], s);
    atomicAdd(&g_sq[f], q);
}

__global__ void bn_final(const float* __restrict__ gamma,
                         const float* __restrict__ beta, int n) {
    int f = threadIdx.x;
    float inv_n = 1.0f / (float)n;
    float mu = g_sum[f] * inv_n;
    float var = g_sq[f] * inv_n - mu * mu;
    float s = gamma[f] * rsqrtf(var + 1e-5f);
    g_scale[f] = s;
    g_shift[f] = beta[f] - mu * s;
}

// ---------------- GEMM 2: out = relu( relu(scale*h+shift) @ W + b ) --------
__global__ __launch_bounds__(256) void gemm_conv2(
    const float* __restrict__ h, const float* __restrict__ W,
    const float* __restrict__ b, float* __restrict__ out, int n) {
    __shared__ float Ws[32 * 128];
    __shared__ float As[32 * 65];
    int t = threadIdx.x;
    int warp = t >> 5, lane = t & 31;
    int row0 = blockIdx.x * 64;

    float acc[8][4];
#pragma unroll
    for (int i = 0; i < 8; i++)
#pragma unroll
        for (int j = 0; j < 4; j++) acc[i][j] = 0.0f;

    for (int kc = 0; kc < 4; kc++) {
#pragma unroll
        for (int i = 0; i < 16; i++) {
            int idx = t + i * 256;
            Ws[idx] = W[kc * 4096 + idx];
        }
#pragma unroll
        for (int i = 0; i < 8; i++) {
            int idx = t + i * 256;
            int row = idx >> 5;
            int kk = idx & 31;
            int r = row0 + row;
            int k = kc * 32 + kk;
            float v = 0.0f;
            if (r < n) {
                float hv = h[(size_t)r * 128 + k];
                v = fmaxf(g_scale[k] * hv + g_shift[k], 0.0f);
            }
            As[kk * 65 + row] = v;
        }
        __syncthreads();
#pragma unroll
        for (int kk = 0; kk < 32; kk++) {
            float4 w = *(const float4*)&Ws[kk * 128 + lane * 4];
#pragma unroll
            for (int i = 0; i < 8; i++) {
                float a = As[kk * 65 + warp * 8 + i];
                acc[i][0] += a * w.x;
                acc[i][1] += a * w.y;
                acc[i][2] += a * w.z;
                acc[i][3] += a * w.w;
            }
        }
        __syncthreads();
    }

    float4 bb = *(const float4*)&b[lane * 4];
#pragma unroll
    for (int i = 0; i < 8; i++) {
        int r = row0 + warp * 8 + i;
        if (r < n) {
            float4 o;
            o.x = fmaxf(acc[i][0] + bb.x, 0.0f);
            o.y = fmaxf(acc[i][1] + bb.y, 0.0f);
            o.z = fmaxf(acc[i][2] + bb.z, 0.0f);
            o.w = fmaxf(acc[i][3] + bb.w, 0.0f);
            *(float4*)&out[(size_t)r * 128 + lane * 4] = o;
        }
    }
}

// ---------------- pooling: segment add + segment max (values >= 0) --------
__global__ void pool_kernel(const float* __restrict__ h,
                            const int* __restrict__ batch,
                            float* __restrict__ psum,
                            unsigned int* __restrict__ pmax, int n) {
    int t = blockIdx.x * blockDim.x + threadIdx.x;
    int node = t >> 5;
    if (node >= n) return;
    int c = t & 31;
    int g = batch[node];
    if ((unsigned)g >= GMAX) return;
    float4 v = ((const float4*)h)[(size_t)node * 32 + c];
    float* sp = psum + g * D + c * 4;
    atomicAdd(sp + 0, v.x);
    atomicAdd(sp + 1, v.y);
    atomicAdd(sp + 2, v.z);
    atomicAdd(sp + 3, v.w);
    unsigned int* mp = pmax + g * D + c * 4;
    atomicMax(mp + 0, __float_as_uint(v.x));
    atomicMax(mp + 1, __float_as_uint(v.y));
    atomicMax(mp + 2, __float_as_uint(v.z));
    atomicMax(mp + 3, __float_as_uint(v.w));
}

// ---------------- readout: [G,512] -> relu(@W1+b1) -> @W2+b2 -> sigmoid ----
// 8 graphs per block, 512 threads (one per column of lin1 output)
__global__ __launch_bounds__(512) void readout_kernel(
    const float* __restrict__ W1, const float* __restrict__ b1,
    const float* __restrict__ W2, const float* __restrict__ b2,
    float* __restrict__ out, int Gn, int write_logits) {
    __shared__ float feats[8][512];
    __shared__ float red[512];
    int c = threadIdx.x;
    int g0 = blockIdx.x * 8;

#pragma unroll
    for (int i = 0; i < 8; i++) {
        int g = g0 + i;
        float v = 0.0f;
        if (g < Gn) {
            if (c < 128)      v = g_pa1[g * D + c];
            else if (c < 256) v = g_pa2[g * D + (c - 128)];
            else if (c < 384) v = __uint_as_float(g_pm1[g * D + (c - 256)]);
            else              v = __uint_as_float(g_pm2[g * D + (c - 384)]);
        }
        feats[i][c] = v;
    }
    __syncthreads();

    float acc[8];
#pragma unroll
    for (int i = 0; i < 8; i++) acc[i] = b1[c];

    for (int k = 0; k < 512; k++) {
        float w = W1[k * 512 + c];
#pragma unroll
        for (int i = 0; i < 8; i++) acc[i] += feats[i][k] * w;
    }

    float l2w = W2[c];
    for (int i = 0; i < 8; i++) {
        red[c] = fmaxf(acc[i], 0.0f) * l2w;
        __syncthreads();
        for (int s = 256; s > 0; s >>= 1) {
            if (c < s) red[c] += red[c + s];
            __syncthreads();
        }
        if (c == 0) {
            int g = g0 + i;
            if (g < Gn) {
                float logit = red[0] + b2[0];
                out[g] = 1.0f / (1.0f + expf(-logit));
                if (write_logits) out[Gn + g] = logit;
            }
        }
        __syncthreads();
    }
}

// ---------------- host ----------------
extern "C" void kernel_launch(void* const* d_in, const int* in_sizes, int n_in,
                              void* d_out, int out_size) {
    const float* x     = (const float*)d_in[0];
    const int*   ei    = (const int*)d_in[1];
    const int*   batch = (const int*)d_in[2];
    const float* c1_W1 = (const float*)d_in[3];
    const float* c1_b1 = (const float*)d_in[4];
    const float* c1_g  = (const float*)d_in[5];
    const float* c1_be = (const float*)d_in[6];
    const float* c1_W2 = (const float*)d_in[7];
    const float* c1_b2 = (const float*)d_in[8];
    const float* c2_W1 = (const float*)d_in[9];
    const float* c2_b1 = (const float*)d_in[10];
    const float* c2_g  = (const float*)d_in[11];
    const float* c2_be = (const float*)d_in[12];
    const float* c2_W2 = (const float*)d_in[13];
    const float* c2_b2 = (const float*)d_in[14];
    const float* lin1_W = (const float*)d_in[15];
    const float* lin1_b = (const float*)d_in[16];
    const float* lin2_W = (const float*)d_in[17];
    const float* lin2_b = (const float*)d_in[18];
    float* out = (float*)d_out;

    int n = in_sizes[0] / D;
    int E = in_sizes[1] / 2;
    int Gn, write_logits;
    if (out_size >= 2 * GMAX) { Gn = out_size / 2; write_logits = 1; }
    else                      { Gn = out_size;     write_logits = 0; }

    float *agg, *h, *h1, *h2, *pa1, *pa2;
    unsigned int *pm1, *pm2;
    cudaGetSymbolAddress((void**)&agg, g_agg);
    cudaGetSymbolAddress((void**)&h,   g_h);
    cudaGetSymbolAddress((void**)&h1,  g_h1);
    cudaGetSymbolAddress((void**)&h2,  g_h2);
    cudaGetSymbolAddress((void**)&pa1, g_pa1);
    cudaGetSymbolAddress((void**)&pa2, g_pa2);
    cudaGetSymbolAddress((void**)&pm1, g_pm1);
    cudaGetSymbolAddress((void**)&pm2, g_pm2);

    int nd = n * D;
    int zeroBlocks = 1024;

    // zero pool buffers
    zero_f<<<256, 256>>>(pa1, GMAX * D);
    zero_f<<<256, 256>>>(pa2, GMAX * D);
    zero_f<<<256, 256>>>((float*)pm1, GMAX * D);
    zero_f<<<256, 256>>>((float*)pm2, GMAX * D);

    int gemmBlocks = (n + 63) / 64;
    int scatterBlocks = (E * 32 + 255) / 256;
    int poolBlocks = (n * 32 + 255) / 256;

    // ---- conv 1 ----
    zero_f<<<zeroBlocks, 256>>>(agg, nd);
    zero_stats<<<1, 128>>>();
    scatter_kernel<<<scatterBlocks, 256>>>(x, ei, agg, E, n);
    gemm_conv1<<<gemmBlocks, 256>>>(agg, x, c1_W1, c1_b1, h, n);
    bn_stats<<<480, 128>>>(h, n);
    bn_final<<<1, 128>>>(c1_g, c1_be, n);
    gemm_conv2<<<gemmBlocks, 256>>>(h, c1_W2, c1_b2, h1, n);
    pool_kernel<<<poolBlocks, 256>>>(h1, batch, pa1, pm1, n);

    // ---- conv 2 ----
    zero_f<<<zeroBlocks, 256>>>(agg, nd);
    zero_stats<<<1, 128>>>();
    scatter_kernel<<<scatterBlocks, 256>>>(h1, ei, agg, E, n);
    gemm_conv1<<<gemmBlocks, 256>>>(agg, h1, c2_W1, c2_b1, h, n);
    bn_stats<<<480, 128>>>(h, n);
    bn_final<<<1, 128>>>(c2_g, c2_be, n);
    gemm_conv2<<<gemmBlocks, 256>>>(h, c2_W2, c2_b2, h2, n);
    pool_kernel<<<poolBlocks, 256>>>(h2, batch, pa2, pm2, n);

    // ---- readout ----
    readout_kernel<<<(Gn + 7) / 8, 512>>>(lin1_W, lin1_b, lin2_W, lin2_b,
                                          out, Gn, write_logits);
}

// round 4
// speedup vs baseline: 1.4496x; 1.4496x over previous
#include <cuda_runtime.h>
#include <math.h>

#define D 128
#define GMAX 512
#define NMAX 50176

typedef unsigned long long ull;

// ---------------- scratch ----------------
__device__ float g_agg[NMAX * D];
__device__ float g_h[NMAX * D];
__device__ float g_h1[NMAX * D];
__device__ float g_h2[NMAX * D];
__device__ float g_sum[D];
__device__ float g_sq[D];
__device__ float g_scale[D];
__device__ float g_shift[D];
__device__ float g_pa1[GMAX * D];
__device__ float g_pa2[GMAX * D];
__device__ unsigned int g_pm1[GMAX * D];
__device__ unsigned int g_pm2[GMAX * D];

// ---------------- f32x2 helpers ----------------
__device__ __forceinline__ ull ffma2(ull a, ull b, ull c) {
    ull d;
    asm("fma.rn.f32x2 %0, %1, %2, %3;" : "=l"(d) : "l"(a), "l"(b), "l"(c));
    return d;
}
__device__ __forceinline__ ull pack2(float a) {
    ull r; unsigned u = __float_as_uint(a);
    asm("mov.b64 %0, {%1, %1};" : "=l"(r) : "r"(u));
    return r;
}
__device__ __forceinline__ float2 unpack2(ull v) {
    unsigned lo, hi;
    asm("mov.b64 {%0, %1}, %2;" : "=r"(lo), "=r"(hi) : "l"(v));
    return make_float2(__uint_as_float(lo), __uint_as_float(hi));
}
__device__ __forceinline__ void red_add_v4(float* p, float4 v) {
    asm volatile("red.global.add.v4.f32 [%0], {%1,%2,%3,%4};"
                 :: "l"(p), "f"(v.x), "f"(v.y), "f"(v.z), "f"(v.w) : "memory");
}
__device__ __forceinline__ void red_max_u32(unsigned* p, unsigned v) {
    asm volatile("red.global.max.u32 [%0], %1;" :: "l"(p), "r"(v) : "memory");
}

// ---------------- copy/init: agg = src; zero stats + pools -----
__global__ void copy_init(const float* __restrict__ src, float* __restrict__ dst,
                          int nd4, float* __restrict__ pa, unsigned* __restrict__ pm) {
    int i = blockIdx.x * blockDim.x + threadIdx.x;
    int stride = gridDim.x * blockDim.x;
    for (int k = i; k < nd4; k += stride)
        ((float4*)dst)[k] = ((const float4*)src)[k];
    for (int k = i; k < GMAX * D / 4; k += stride) {
        ((float4*)pa)[k] = make_float4(0.f, 0.f, 0.f, 0.f);
        ((uint4*)pm)[k] = make_uint4(0u, 0u, 0u, 0u);
    }
    if (i < D) { g_sum[i] = 0.0f; g_sq[i] = 0.0f; }
}

// ---------------- edge scatter: agg[dst] += x[src] (one warp per edge) -----
__global__ void scatter_kernel(const float* __restrict__ x,
                               const int* __restrict__ ei,
                               float* __restrict__ agg, int n_edges, int n) {
    int t = blockIdx.x * blockDim.x + threadIdx.x;
    int e = t >> 5;
    if (e >= n_edges) return;
    int c = t & 31;
    int src = ei[e];
    int dst = ei[n_edges + e];
    if ((unsigned)src >= (unsigned)n || (unsigned)dst >= (unsigned)n) return;
    float4 v = ((const float4*)x)[(size_t)src * 32 + c];
    red_add_v4(agg + (size_t)dst * D + c * 4, v);
}

// =================== GEMM stage 1: h = A @ W + b, + BN stats ===============
// 128x128 tile, 256 threads, 8x8 per thread via f32x2.
__global__ __launch_bounds__(256) void gemm_stats(
    const float* __restrict__ A, const float* __restrict__ W,
    const float* __restrict__ b, float* __restrict__ out, int n) {
    __shared__ float As[128][36];
    __shared__ float Ws[32][136];
    int t = threadIdx.x;
    int tx = t & 15, ty = t >> 4;
    int r0 = blockIdx.x * 128;

    ull acc[8][4];
#pragma unroll
    for (int i = 0; i < 8; i++)
#pragma unroll
        for (int j = 0; j < 4; j++) acc[i][j] = 0ull;

    for (int kc = 0; kc < 4; kc++) {
#pragma unroll
        for (int i = 0; i < 4; i++) {
            int f = t + i * 256;
            int kk = f >> 5, c4 = (f & 31) * 4;
            *(float4*)&Ws[kk][c4] = *(const float4*)&W[kc * 4096 + kk * 128 + c4];
        }
#pragma unroll
        for (int i = 0; i < 4; i++) {
            int f = t + i * 256;
            int row = f >> 3, c4 = (f & 7) * 4;
            float4 v = make_float4(0.f, 0.f, 0.f, 0.f);
            int r = r0 + row;
            if (r < n) v = *(const float4*)&A[(size_t)r * 128 + kc * 32 + c4];
            *(float4*)&As[row][c4] = v;
        }
        __syncthreads();
#pragma unroll 8
        for (int kk = 0; kk < 32; kk++) {
            ull w[4];
#pragma unroll
            for (int j = 0; j < 4; j++) w[j] = *(const ull*)&Ws[kk][tx * 8 + 2 * j];
#pragma unroll
            for (int i = 0; i < 8; i++) {
                ull a2 = pack2(As[ty * 8 + i][kk]);
#pragma unroll
                for (int j = 0; j < 4; j++) acc[i][j] = ffma2(a2, w[j], acc[i][j]);
            }
        }
        __syncthreads();
    }

    // epilogue: bias, store, column stats
    float4 b0 = *(const float4*)&b[tx * 8];
    float4 b1 = *(const float4*)&b[tx * 8 + 4];
    float bias[8] = {b0.x, b0.y, b0.z, b0.w, b1.x, b1.y, b1.z, b1.w};
    float s[8], q[8];
#pragma unroll
    for (int j = 0; j < 8; j++) { s[j] = 0.f; q[j] = 0.f; }

#pragma unroll
    for (int i = 0; i < 8; i++) {
        float o[8];
#pragma unroll
        for (int j = 0; j < 4; j++) {
            float2 p = unpack2(acc[i][j]);
            o[2 * j] = p.x + bias[2 * j];
            o[2 * j + 1] = p.y + bias[2 * j + 1];
        }
        int r = r0 + ty * 8 + i;
        if (r < n) {
            *(float4*)&out[(size_t)r * 128 + tx * 8]     = make_float4(o[0], o[1], o[2], o[3]);
            *(float4*)&out[(size_t)r * 128 + tx * 8 + 4] = make_float4(o[4], o[5], o[6], o[7]);
#pragma unroll
            for (int j = 0; j < 8; j++) { s[j] += o[j]; q[j] += o[j] * o[j]; }
        }
    }

    // cross-thread column reduction in smem (reuse As storage)
    float* redS = &As[0][0];          // 16*128 floats
    float* redQ = &As[0][0] + 2048;   // next 16*128
#pragma unroll
    for (int j = 0; j < 8; j++) {
        redS[ty * 128 + tx * 8 + j] = s[j];
        redQ[ty * 128 + tx * 8 + j] = q[j];
    }
    __syncthreads();
    if (t < 128) {
        float ss = 0.f, qq = 0.f;
#pragma unroll
        for (int g = 0; g < 16; g++) {
            ss += redS[g * 128 + t];
            qq += redQ[g * 128 + t];
        }
        atomicAdd(&g_sum[t], ss);
        atomicAdd(&g_sq[t], qq);
    }
}

__global__ void bn_final(const float* __restrict__ gamma,
                         const float* __restrict__ beta, int n) {
    int f = threadIdx.x;
    float inv_n = 1.0f / (float)n;
    float mu = g_sum[f] * inv_n;
    float var = g_sq[f] * inv_n - mu * mu;
    float s = gamma[f] * rsqrtf(var + 1e-5f);
    g_scale[f] = s;
    g_shift[f] = beta[f] - mu * s;
}

// ========== GEMM stage 2: out = relu( relu(scale*h+shift) @ W + b ) ========
__global__ __launch_bounds__(256) void gemm_bnrelu(
    const float* __restrict__ A, const float* __restrict__ W,
    const float* __restrict__ b, float* __restrict__ out, int n) {
    __shared__ float As[128][36];
    __shared__ float Ws[32][136];
    int t = threadIdx.x;
    int tx = t & 15, ty = t >> 4;
    int r0 = blockIdx.x * 128;

    ull acc[8][4];
#pragma unroll
    for (int i = 0; i < 8; i++)
#pragma unroll
        for (int j = 0; j < 4; j++) acc[i][j] = 0ull;

    for (int kc = 0; kc < 4; kc++) {
#pragma unroll
        for (int i = 0; i < 4; i++) {
            int f = t + i * 256;
            int kk = f >> 5, c4 = (f & 31) * 4;
            *(float4*)&Ws[kk][c4] = *(const float4*)&W[kc * 4096 + kk * 128 + c4];
        }
#pragma unroll
        for (int i = 0; i < 4; i++) {
            int f = t + i * 256;
            int row = f >> 3, c4 = (f & 7) * 4;
            float4 v = make_float4(0.f, 0.f, 0.f, 0.f);
            int r = r0 + row;
            int k = kc * 32 + c4;
            if (r < n) {
                float4 h = *(const float4*)&A[(size_t)r * 128 + k];
                v.x = fmaxf(g_scale[k + 0] * h.x + g_shift[k + 0], 0.f);
                v.y = fmaxf(g_scale[k + 1] * h.y + g_shift[k + 1], 0.f);
                v.z = fmaxf(g_scale[k + 2] * h.z + g_shift[k + 2], 0.f);
                v.w = fmaxf(g_scale[k + 3] * h.w + g_shift[k + 3], 0.f);
            }
            *(float4*)&As[row][c4] = v;
        }
        __syncthreads();
#pragma unroll 8
        for (int kk = 0; kk < 32; kk++) {
            ull w[4];
#pragma unroll
            for (int j = 0; j < 4; j++) w[j] = *(const ull*)&Ws[kk][tx * 8 + 2 * j];
#pragma unroll
            for (int i = 0; i < 8; i++) {
                ull a2 = pack2(As[ty * 8 + i][kk]);
#pragma unroll
                for (int j = 0; j < 4; j++) acc[i][j] = ffma2(a2, w[j], acc[i][j]);
            }
        }
        __syncthreads();
    }

    float4 b0 = *(const float4*)&b[tx * 8];
    float4 b1 = *(const float4*)&b[tx * 8 + 4];
    float bias[8] = {b0.x, b0.y, b0.z, b0.w, b1.x, b1.y, b1.z, b1.w};

#pragma unroll
    for (int i = 0; i < 8; i++) {
        int r = r0 + ty * 8 + i;
        if (r < n) {
            float o[8];
#pragma unroll
            for (int j = 0; j < 4; j++) {
                float2 p = unpack2(acc[i][j]);
                o[2 * j] = fmaxf(p.x + bias[2 * j], 0.f);
                o[2 * j + 1] = fmaxf(p.y + bias[2 * j + 1], 0.f);
            }
            *(float4*)&out[(size_t)r * 128 + tx * 8]     = make_float4(o[0], o[1], o[2], o[3]);
            *(float4*)&out[(size_t)r * 128 + tx * 8 + 4] = make_float4(o[4], o[5], o[6], o[7]);
        }
    }
}

// ---------------- pooling ----------------
__global__ void pool_kernel(const float* __restrict__ h,
                            const int* __restrict__ batch,
                            float* __restrict__ psum,
                            unsigned int* __restrict__ pmax, int n) {
    int t = blockIdx.x * blockDim.x + threadIdx.x;
    int node = t >> 5;
    if (node >= n) return;
    int c = t & 31;
    int g = batch[node];
    if ((unsigned)g >= GMAX) return;
    float4 v = ((const float4*)h)[(size_t)node * 32 + c];
    red_add_v4(psum + g * D + c * 4, v);
    unsigned* mp = pmax + g * D + c * 4;
    red_max_u32(mp + 0, __float_as_uint(v.x));
    red_max_u32(mp + 1, __float_as_uint(v.y));
    red_max_u32(mp + 2, __float_as_uint(v.z));
    red_max_u32(mp + 3, __float_as_uint(v.w));
}

// ---------------- readout ----------------
__global__ __launch_bounds__(512) void readout_kernel(
    const float* __restrict__ W1, const float* __restrict__ b1,
    const float* __restrict__ W2, const float* __restrict__ b2,
    float* __restrict__ out, int Gn, int write_logits) {
    __shared__ float feats[8][512];
    __shared__ float red[512];
    int c = threadIdx.x;
    int g0 = blockIdx.x * 8;

#pragma unroll
    for (int i = 0; i < 8; i++) {
        int g = g0 + i;
        float v = 0.0f;
        if (g < Gn) {
            if (c < 128)      v = g_pa1[g * D + c];
            else if (c < 256) v = g_pa2[g * D + (c - 128)];
            else if (c < 384) v = __uint_as_float(g_pm1[g * D + (c - 256)]);
            else              v = __uint_as_float(g_pm2[g * D + (c - 384)]);
        }
        feats[i][c] = v;
    }
    __syncthreads();

    float acc[8];
#pragma unroll
    for (int i = 0; i < 8; i++) acc[i] = b1[c];

    for (int k = 0; k < 512; k++) {
        float w = W1[k * 512 + c];
#pragma unroll
        for (int i = 0; i < 8; i++) acc[i] += feats[i][k] * w;
    }

    float l2w = W2[c];
    for (int i = 0; i < 8; i++) {
        red[c] = fmaxf(acc[i], 0.0f) * l2w;
        __syncthreads();
        for (int s = 256; s > 0; s >>= 1) {
            if (c < s) red[c] += red[c + s];
            __syncthreads();
        }
        if (c == 0) {
            int g = g0 + i;
            if (g < Gn) {
                float logit = red[0] + b2[0];
                out[g] = 1.0f / (1.0f + expf(-logit));
                if (write_logits) out[Gn + g] = logit;
            }
        }
        __syncthreads();
    }
}

// ---------------- host ----------------
extern "C" void kernel_launch(void* const* d_in, const int* in_sizes, int n_in,
                              void* d_out, int out_size) {
    const float* x     = (const float*)d_in[0];
    const int*   ei    = (const int*)d_in[1];
    const int*   batch = (const int*)d_in[2];
    const float* c1_W1 = (const float*)d_in[3];
    const float* c1_b1 = (const float*)d_in[4];
    const float* c1_g  = (const float*)d_in[5];
    const float* c1_be = (const float*)d_in[6];
    const float* c1_W2 = (const float*)d_in[7];
    const float* c1_b2 = (const float*)d_in[8];
    const float* c2_W1 = (const float*)d_in[9];
    const float* c2_b1 = (const float*)d_in[10];
    const float* c2_g  = (const float*)d_in[11];
    const float* c2_be = (const float*)d_in[12];
    const float* c2_W2 = (const float*)d_in[13];
    const float* c2_b2 = (const float*)d_in[14];
    const float* lin1_W = (const float*)d_in[15];
    const float* lin1_b = (const float*)d_in[16];
    const float* lin2_W = (const float*)d_in[17];
    const float* lin2_b = (const float*)d_in[18];
    float* out = (float*)d_out;

    int n = in_sizes[0] / D;
    int E = in_sizes[1] / 2;
    int Gn, write_logits;
    if (out_size >= 2 * GMAX) { Gn = out_size / 2; write_logits = 1; }
    else                      { Gn = out_size;     write_logits = 0; }

    float *agg, *h, *h1, *h2, *pa1, *pa2;
    unsigned int *pm1, *pm2;
    cudaGetSymbolAddress((void**)&agg, g_agg);
    cudaGetSymbolAddress((void**)&h,   g_h);
    cudaGetSymbolAddress((void**)&h1,  g_h1);
    cudaGetSymbolAddress((void**)&h2,  g_h2);
    cudaGetSymbolAddress((void**)&pa1, g_pa1);
    cudaGetSymbolAddress((void**)&pa2, g_pa2);
    cudaGetSymbolAddress((void**)&pm1, g_pm1);
    cudaGetSymbolAddress((void**)&pm2, g_pm2);

    int nd4 = n * D / 4;
    int gemmBlocks = (n + 127) / 128;
    int scatterBlocks = (E * 32 + 255) / 256;
    int poolBlocks = (n * 32 + 255) / 256;

    // ---- conv 1 ----
    copy_init<<<512, 256>>>(x, agg, nd4, pa1, pm1);                    // agg = x (self term)
    scatter_kernel<<<scatterBlocks, 256>>>(x, ei, agg, E, n);          // agg += sum neighbors
    gemm_stats<<<gemmBlocks, 256>>>(agg, c1_W1, c1_b1, h, n);
    bn_final<<<1, 128>>>(c1_g, c1_be, n);
    gemm_bnrelu<<<gemmBlocks, 256>>>(h, c1_W2, c1_b2, h1, n);
    pool_kernel<<<poolBlocks, 256>>>(h1, batch, pa1, pm1, n);

    // ---- conv 2 ----
    copy_init<<<512, 256>>>(h1, agg, nd4, pa2, pm2);
    scatter_kernel<<<scatterBlocks, 256>>>(h1, ei, agg, E, n);
    gemm_stats<<<gemmBlocks, 256>>>(agg, c2_W1, c2_b1, h, n);
    bn_final<<<1, 128>>>(c2_g, c2_be, n);
    gemm_bnrelu<<<gemmBlocks, 256>>>(h, c2_W2, c2_b2, h2, n);
    pool_kernel<<<poolBlocks, 256>>>(h2, batch, pa2, pm2, n);

    // ---- readout ----
    readout_kernel<<<(Gn + 7) / 8, 512>>>(lin1_W, lin1_b, lin2_W, lin2_b,
                                          out, Gn, write_logits);
}